// round 3
// baseline (speedup 1.0000x reference)
#include <cuda_runtime.h>

// ApproximateConv2d: z[b,o,h,w] = mu_w * sum_{c,kh,kw} min(x_pad, w)
// x: (4,32,56,56) f32, w: (64,32,3,3) f32, out: (4,64,56,56) f32
//
// Strategy: channel-split x2 into a partial buffer (more warps/SM), packed
// f32x2 accumulation (halve fma-pipe adds), combine kernel applies mu.

#define Bn 4
#define Cn 32
#define Hn 56
#define Wn 56
#define On 64
#define KK 9
#define CKK 288

#define TO 8              // output channels per thread
#define OG (On / TO)      // 8
#define TH 4              // output rows per block
#define NBAND (Hn / TH)   // 14
#define THREADS (TH * Wn) // 224

#define CCH 16            // channels per block (half of Cn)
#define LCK (CCH * KK)    // 144 local ck entries
#define XS_ROWS (TH + 2)  // 6
#define XS_COLS (Wn + 2)  // 58
#define XS_PLANE (XS_ROWS * XS_COLS)
#define XS_SIZE (CCH * XS_PLANE)

#define NOUT (Bn * On * Hn * Wn)   // 802816

__device__ float g_mu;
__device__ float g_part[2 * NOUT]; // two channel-half partials

// ---------------------------------------------------------------------------
// mu_w = mean(|w|)
// ---------------------------------------------------------------------------
__global__ void mu_kernel(const float* __restrict__ w) {
    __shared__ float red[256];
    const int n4 = (On * CKK) / 4;
    const float4* w4 = reinterpret_cast<const float4*>(w);
    float s = 0.f;
    for (int i = threadIdx.x; i < n4; i += 256) {
        float4 v = w4[i];
        s += fabsf(v.x) + fabsf(v.y) + fabsf(v.z) + fabsf(v.w);
    }
    red[threadIdx.x] = s;
    __syncthreads();
    for (int off = 128; off > 0; off >>= 1) {
        if (threadIdx.x < off) red[threadIdx.x] += red[threadIdx.x + off];
        __syncthreads();
    }
    if (threadIdx.x == 0) g_mu = red[0] / (float)(On * CKK);
}

// min two lanes against xv, pack, packed-accumulate (Blackwell f32x2).
__device__ __forceinline__ void min2_acc(unsigned long long& acc, float xv,
                                         float we, float wo) {
    asm("{\n\t"
        ".reg .f32 a, b;\n\t"
        ".reg .b64 t;\n\t"
        "min.f32 a, %1, %2;\n\t"
        "min.f32 b, %1, %3;\n\t"
        "mov.b64 t, {a, b};\n\t"
        "add.rn.f32x2 %0, %0, t;\n\t"
        "}"
        : "+l"(acc) : "f"(xv), "f"(we), "f"(wo));
}

// ---------------------------------------------------------------------------
// Main kernel: grid = (OG=8, NBAND=14, Bn*2=8) = 896 blocks, 224 threads.
// blockIdx.z = b*2 + half; each block does 16 input channels, TO=8 outputs.
// ---------------------------------------------------------------------------
__global__ __launch_bounds__(THREADS, 4)
void approx_conv_kernel(const float* __restrict__ x,
                        const float* __restrict__ w) {
    __shared__ __align__(16) float ws[LCK * TO];  // 4608 B
    __shared__ float xs[XS_SIZE];                 // 22272 B

    const int tid   = threadIdx.x;
    const int og    = blockIdx.x;
    const int band  = blockIdx.y;
    const int zb    = blockIdx.z;
    const int b     = zb >> 1;
    const int half  = zb & 1;
    const int obase = og * TO;
    const int hbase = band * TH;
    const int cbase = half * CCH;

    // Weights: ws[lck*TO + oo] = w[(obase+oo)*CKK + half*LCK + lck]
    for (int i = tid; i < LCK * TO; i += THREADS) {
        int lck = i / TO;
        int oo  = i % TO;
        ws[i] = w[(obase + oo) * CKK + half * LCK + lck];
    }

    // x stage: 16 channels, padded 6x58
    for (int i = tid; i < XS_SIZE; i += THREADS) {
        int cc  = i / XS_PLANE;
        int rem = i % XS_PLANE;
        int r   = rem / XS_COLS;
        int cl  = rem % XS_COLS;
        int gh  = hbase + r - 1;
        int gw  = cl - 1;
        float v = 0.f;
        if (gh >= 0 && gh < Hn && gw >= 0 && gw < Wn)
            v = x[((b * Cn + cbase + cc) * Hn + gh) * Wn + gw];
        xs[i] = v;
    }
    __syncthreads();

    const int row = tid / Wn;
    const int col = tid % Wn;

    unsigned long long acc[4] = {0ull, 0ull, 0ull, 0ull};

#pragma unroll 4
    for (int cc = 0; cc < CCH; cc++) {
        const float* xbase = &xs[cc * XS_PLANE + row * XS_COLS + col];
        // batch the 9 window loads
        float xv[9];
#pragma unroll
        for (int kh = 0; kh < 3; kh++)
#pragma unroll
            for (int kw = 0; kw < 3; kw++)
                xv[kh * 3 + kw] = xbase[kh * XS_COLS + kw];

        const float4* wp4 = reinterpret_cast<const float4*>(&ws[cc * KK * TO]);
#pragma unroll
        for (int p = 0; p < 9; p++) {
            float4 w0 = wp4[p * 2 + 0];
            float4 w1 = wp4[p * 2 + 1];
            float v = xv[p];
            min2_acc(acc[0], v, w0.x, w0.y);
            min2_acc(acc[1], v, w0.z, w0.w);
            min2_acc(acc[2], v, w1.x, w1.y);
            min2_acc(acc[3], v, w1.z, w1.w);
        }
    }

    const int h = hbase + row;
    float* dst = &g_part[half * NOUT + ((b * On + obase) * Hn + h) * Wn + col];
#pragma unroll
    for (int i = 0; i < 4; i++) {
        unsigned int lo = (unsigned int)(acc[i] & 0xffffffffull);
        unsigned int hi = (unsigned int)(acc[i] >> 32);
        dst[(2 * i + 0) * Hn * Wn] = __uint_as_float(lo);
        dst[(2 * i + 1) * Hn * Wn] = __uint_as_float(hi);
    }
}

// ---------------------------------------------------------------------------
// Combine: out = mu * (part0 + part1), vectorized float4
// ---------------------------------------------------------------------------
__global__ __launch_bounds__(256)
void combine_kernel(float* __restrict__ out) {
    const int n4 = NOUT / 4; // 200704
    const float4* p0 = reinterpret_cast<const float4*>(&g_part[0]);
    const float4* p1 = reinterpret_cast<const float4*>(&g_part[NOUT]);
    float4* o4 = reinterpret_cast<float4*>(out);
    const float mu = g_mu;
    int i = blockIdx.x * blockDim.x + threadIdx.x;
    if (i < n4) {
        float4 a = p0[i];
        float4 bq = p1[i];
        float4 r;
        r.x = mu * (a.x + bq.x);
        r.y = mu * (a.y + bq.y);
        r.z = mu * (a.z + bq.z);
        r.w = mu * (a.w + bq.w);
        o4[i] = r;
    }
}

extern "C" void kernel_launch(void* const* d_in, const int* in_sizes, int n_in,
                              void* d_out, int out_size) {
    const float* x = (const float*)d_in[0];
    const float* w = (const float*)d_in[1];
    float* out = (float*)d_out;

    mu_kernel<<<1, 256>>>(w);

    dim3 grid(OG, NBAND, Bn * 2);
    approx_conv_kernel<<<grid, THREADS>>>(x, w);

    combine_kernel<<<(NOUT / 4 + 255) / 256, 256>>>(out);
}

// round 4
// speedup vs baseline: 1.3521x; 1.3521x over previous
#include <cuda_runtime.h>

// ApproximateConv2d: z[b,o,h,w] = mu_w * sum_{c,kh,kw} min(x_pad, w)
// x: (4,32,56,56) f32, w: (64,32,3,3) f32, out: (4,64,56,56) f32

#define Bn 4
#define Cn 32
#define Hn 56
#define Wn 56
#define On 64
#define KK 9
#define CKK 288

#define TO 4              // output channels per thread
#define OG (On / TO)      // 16
#define TH 4              // output rows per block
#define NBAND (Hn / TH)   // 14
#define THREADS (TH * Wn) // 224

#define CCHUNK 16
#define NCHUNK (Cn / CCHUNK) // 2
#define XS_ROWS (TH + 2)     // 6
#define XS_COLS (Wn + 2)     // 58
#define XS_PLANE (XS_ROWS * XS_COLS)
#define XS_SIZE (CCHUNK * XS_PLANE)

__device__ float g_mu;

// ---------------------------------------------------------------------------
// mu_w = mean(|w|): one block, 1024 threads, shuffle reduce (latency-lean)
// ---------------------------------------------------------------------------
__global__ __launch_bounds__(1024)
void mu_kernel(const float* __restrict__ w) {
    __shared__ float red[32];
    const int n4 = (On * CKK) / 4; // 4608
    const float4* w4 = reinterpret_cast<const float4*>(w);
    float s = 0.f;
    for (int i = threadIdx.x; i < n4; i += 1024) {
        float4 v = w4[i];
        s += fabsf(v.x) + fabsf(v.y) + fabsf(v.z) + fabsf(v.w);
    }
#pragma unroll
    for (int off = 16; off > 0; off >>= 1)
        s += __shfl_xor_sync(0xffffffffu, s, off);
    if ((threadIdx.x & 31) == 0) red[threadIdx.x >> 5] = s;
    __syncthreads();
    if (threadIdx.x < 32) {
        float t = red[threadIdx.x];
#pragma unroll
        for (int off = 16; off > 0; off >>= 1)
            t += __shfl_xor_sync(0xffffffffu, t, off);
        if (threadIdx.x == 0) g_mu = t / (float)(On * CKK);
    }
}

// ---------------------------------------------------------------------------
// Main kernel.
// grid = (OG=16, NBAND=14, Bn=4) = 896 blocks; block = 224 threads.
// thread = one output pixel in a 4x56 band, TO=4 output channels.
// ---------------------------------------------------------------------------
__global__ __launch_bounds__(THREADS, 6)
void approx_conv_kernel(const float* __restrict__ x,
                        const float* __restrict__ w,
                        float* __restrict__ out) {
    __shared__ __align__(16) float ws[CKK * TO];  // 4608 B
    __shared__ float xs[XS_SIZE];                 // 22272 B

    const int tid   = threadIdx.x;
    const int og    = blockIdx.x;
    const int band  = blockIdx.y;
    const int b     = blockIdx.z;
    const int obase = og * TO;
    const int hbase = band * TH;

    // Weights transposed: ws[ck*TO + oo] = w[(obase+oo)*CKK + ck]
    for (int i = tid; i < CKK * TO; i += THREADS) {
        int ck = i / TO;
        int oo = i % TO;
        ws[i] = w[(obase + oo) * CKK + ck];
    }

    const int row = tid / Wn;  // 0..3
    const int col = tid % Wn;  // 0..55

    float acc0 = 0.f, acc1 = 0.f, acc2 = 0.f, acc3 = 0.f;

    for (int ch = 0; ch < NCHUNK; ch++) {
        __syncthreads();
        // Stage 16 channels of x, padded 6x58, zeros outside image
        for (int i = tid; i < XS_SIZE; i += THREADS) {
            int cc  = i / XS_PLANE;
            int rem = i % XS_PLANE;
            int r   = rem / XS_COLS;
            int cl  = rem % XS_COLS;
            int gh  = hbase + r - 1;
            int gw  = cl - 1;
            float v = 0.f;
            if (gh >= 0 && gh < Hn && gw >= 0 && gw < Wn)
                v = x[((b * Cn + ch * CCHUNK + cc) * Hn + gh) * Wn + gw];
            xs[i] = v;
        }
        __syncthreads();

#pragma unroll 4
        for (int cc = 0; cc < CCHUNK; cc++) {
            const float* xbase = &xs[cc * XS_PLANE + row * XS_COLS + col];
            float xv[9];
#pragma unroll
            for (int kh = 0; kh < 3; kh++)
#pragma unroll
                for (int kw = 0; kw < 3; kw++)
                    xv[kh * 3 + kw] = xbase[kh * XS_COLS + kw];

            const float4* wp4 = reinterpret_cast<const float4*>(
                &ws[(ch * CCHUNK + cc) * KK * TO]);
#pragma unroll
            for (int p = 0; p < 9; p++) {
                float4 wv = wp4[p];
                float v = xv[p];
                acc0 += fminf(v, wv.x);
                acc1 += fminf(v, wv.y);
                acc2 += fminf(v, wv.z);
                acc3 += fminf(v, wv.w);
            }
        }
    }

    const float mu = g_mu;
    const int h = hbase + row;
    float* dst = &out[((b * On + obase) * Hn + h) * Wn + col];
    dst[0 * Hn * Wn] = mu * acc0;
    dst[1 * Hn * Wn] = mu * acc1;
    dst[2 * Hn * Wn] = mu * acc2;
    dst[3 * Hn * Wn] = mu * acc3;
}

extern "C" void kernel_launch(void* const* d_in, const int* in_sizes, int n_in,
                              void* d_out, int out_size) {
    const float* x = (const float*)d_in[0];
    const float* w = (const float*)d_in[1];
    float* out = (float*)d_out;

    mu_kernel<<<1, 1024>>>(w);

    dim3 grid(OG, NBAND, Bn);
    approx_conv_kernel<<<grid, THREADS>>>(x, w, out);
}

// round 6
// speedup vs baseline: 1.4213x; 1.0511x over previous
#include <cuda_runtime.h>

// ApproximateConv2d: z[b,o,h,w] = mu_w * sum_{c,kh,kw} min(x_pad, w)
// x: (4,32,56,56) f32, w: (64,32,3,3) f32, out: (4,64,56,56) f32
//
// R6 = R4 (TO=4, 896 blocks) + packed f32x2 accumulation:
//   two scalar FMNMX -> mov.b64 pack -> one add.rn.f32x2  (fma-pipe ops halved)

#define Bn 4
#define Cn 32
#define Hn 56
#define Wn 56
#define On 64
#define KK 9
#define CKK 288

#define TO 4              // output channels per thread
#define OG (On / TO)      // 16
#define TH 4              // output rows per block
#define NBAND (Hn / TH)   // 14
#define THREADS (TH * Wn) // 224

#define CCHUNK 16
#define NCHUNK (Cn / CCHUNK) // 2
#define XS_ROWS (TH + 2)     // 6
#define XS_COLS (Wn + 2)     // 58
#define XS_PLANE (XS_ROWS * XS_COLS)
#define XS_SIZE (CCHUNK * XS_PLANE)

__device__ float g_mu;

// two mins against xv, pack, packed-accumulate (add.rn.f32x2 is valid sm_10x PTX)
__device__ __forceinline__ void min2_acc(unsigned long long& acc, float xv,
                                         float wa, float wb) {
    float a = fminf(xv, wa);
    float b = fminf(xv, wb);
    unsigned long long t;
    asm("mov.b64 %0, {%1, %2};" : "=l"(t) : "f"(a), "f"(b));
    asm("add.rn.f32x2 %0, %0, %1;" : "+l"(acc) : "l"(t));
}

__device__ __forceinline__ void unpack2(unsigned long long a, float& lo, float& hi) {
    asm("mov.b64 {%0, %1}, %2;" : "=f"(lo), "=f"(hi) : "l"(a));
}

// ---------------------------------------------------------------------------
// mu_w = mean(|w|): one block, 1024 threads, shuffle reduce
// ---------------------------------------------------------------------------
__global__ __launch_bounds__(1024)
void mu_kernel(const float* __restrict__ w) {
    __shared__ float red[32];
    const int n4 = (On * CKK) / 4; // 4608
    const float4* w4 = reinterpret_cast<const float4*>(w);
    float s = 0.f;
    for (int i = threadIdx.x; i < n4; i += 1024) {
        float4 v = w4[i];
        s += fabsf(v.x) + fabsf(v.y) + fabsf(v.z) + fabsf(v.w);
    }
#pragma unroll
    for (int off = 16; off > 0; off >>= 1)
        s += __shfl_xor_sync(0xffffffffu, s, off);
    if ((threadIdx.x & 31) == 0) red[threadIdx.x >> 5] = s;
    __syncthreads();
    if (threadIdx.x < 32) {
        float t = red[threadIdx.x];
#pragma unroll
        for (int off = 16; off > 0; off >>= 1)
            t += __shfl_xor_sync(0xffffffffu, t, off);
        if (threadIdx.x == 0) g_mu = t / (float)(On * CKK);
    }
}

// ---------------------------------------------------------------------------
// Main kernel. grid = (16, 14, 4) = 896 blocks, 224 threads.
// Thread = one output pixel in a 4x56 band, TO=4 output channels,
// accumulated in two packed f32x2 registers.
// ---------------------------------------------------------------------------
__global__ __launch_bounds__(THREADS, 6)
void approx_conv_kernel(const float* __restrict__ x,
                        const float* __restrict__ w,
                        float* __restrict__ out) {
    __shared__ __align__(16) float ws[CKK * TO];  // 4608 B
    __shared__ float xs[XS_SIZE];                 // 22272 B

    const int tid   = threadIdx.x;
    const int og    = blockIdx.x;
    const int band  = blockIdx.y;
    const int b     = blockIdx.z;
    const int obase = og * TO;
    const int hbase = band * TH;

    // Weights transposed: ws[ck*TO + oo] = w[(obase+oo)*CKK + ck]
    for (int i = tid; i < CKK * TO; i += THREADS) {
        int ck = i / TO;
        int oo = i % TO;
        ws[i] = w[(obase + oo) * CKK + ck];
    }

    const int row = tid / Wn;  // 0..3
    const int col = tid % Wn;  // 0..55

    unsigned long long acc01 = 0ull, acc23 = 0ull;  // packed +0.0f pairs

    for (int ch = 0; ch < NCHUNK; ch++) {
        __syncthreads();
        // Stage 16 channels of x, padded 6x58, zeros outside image
        for (int i = tid; i < XS_SIZE; i += THREADS) {
            int cc  = i / XS_PLANE;
            int rem = i % XS_PLANE;
            int r   = rem / XS_COLS;
            int cl  = rem % XS_COLS;
            int gh  = hbase + r - 1;
            int gw  = cl - 1;
            float v = 0.f;
            if (gh >= 0 && gh < Hn && gw >= 0 && gw < Wn)
                v = x[((b * Cn + ch * CCHUNK + cc) * Hn + gh) * Wn + gw];
            xs[i] = v;
        }
        __syncthreads();

#pragma unroll 4
        for (int cc = 0; cc < CCHUNK; cc++) {
            const float* xbase = &xs[cc * XS_PLANE + row * XS_COLS + col];
            float xv[9];
#pragma unroll
            for (int kh = 0; kh < 3; kh++)
#pragma unroll
                for (int kw = 0; kw < 3; kw++)
                    xv[kh * 3 + kw] = xbase[kh * XS_COLS + kw];

            const float4* wp4 = reinterpret_cast<const float4*>(
                &ws[(ch * CCHUNK + cc) * KK * TO]);
#pragma unroll
            for (int p = 0; p < 9; p++) {
                float4 wv = wp4[p];   // LDS.128 broadcast
                float v = xv[p];
                min2_acc(acc01, v, wv.x, wv.y);
                min2_acc(acc23, v, wv.z, wv.w);
            }
        }
    }

    const float mu = g_mu;
    float a0, a1, a2, a3;
    unpack2(acc01, a0, a1);
    unpack2(acc23, a2, a3);

    const int h = hbase + row;
    float* dst = &out[((b * On + obase) * Hn + h) * Wn + col];
    dst[0 * Hn * Wn] = mu * a0;
    dst[1 * Hn * Wn] = mu * a1;
    dst[2 * Hn * Wn] = mu * a2;
    dst[3 * Hn * Wn] = mu * a3;
}

extern "C" void kernel_launch(void* const* d_in, const int* in_sizes, int n_in,
                              void* d_out, int out_size) {
    const float* x = (const float*)d_in[0];
    const float* w = (const float*)d_in[1];
    float* out = (float*)d_out;

    mu_kernel<<<1, 1024>>>(w);

    dim3 grid(OG, NBAND, Bn);
    approx_conv_kernel<<<grid, THREADS>>>(x, w, out);
}

// round 7
// speedup vs baseline: 1.9221x; 1.3524x over previous
#include <cuda_runtime.h>
#include <cuda_fp16.h>

// ApproximateConv2d: z[b,o,h,w] = mu_w * sum_{c,kh,kw} min(x_pad, w)
// x: (4,32,56,56) f32, w: (64,32,3,3) f32, out: (4,64,56,56) f32
//
// R7: packed-fp16 inner math. min+add on half2 (2 contribs/op), per-input-
// channel (9-term) chunks flushed into fp32 accumulators.

#define Bn 4
#define Cn 32
#define Hn 56
#define Wn 56
#define On 64
#define KK 9
#define CKK 288

#define TO 8              // output channels per thread (one LDS.128 of halves)
#define OG (On / TO)      // 8
#define TH 4              // output rows per block
#define NBAND (Hn / TH)   // 14
#define THREADS (TH * Wn) // 224

#define CCHUNK 16
#define NCHUNK (Cn / CCHUNK) // 2
#define XS_ROWS (TH + 2)     // 6
#define XS_COLS (Wn + 2)     // 58
#define XS_PLANE (XS_ROWS * XS_COLS)
#define XS_SIZE (CCHUNK * XS_PLANE)

__device__ float g_mu;

// ---------------------------------------------------------------------------
// mu_w = mean(|w|) in fp32 (exact)
// ---------------------------------------------------------------------------
__global__ __launch_bounds__(1024)
void mu_kernel(const float* __restrict__ w) {
    __shared__ float red[32];
    const int n4 = (On * CKK) / 4; // 4608
    const float4* w4 = reinterpret_cast<const float4*>(w);
    float s = 0.f;
    for (int i = threadIdx.x; i < n4; i += 1024) {
        float4 v = w4[i];
        s += fabsf(v.x) + fabsf(v.y) + fabsf(v.z) + fabsf(v.w);
    }
#pragma unroll
    for (int off = 16; off > 0; off >>= 1)
        s += __shfl_xor_sync(0xffffffffu, s, off);
    if ((threadIdx.x & 31) == 0) red[threadIdx.x >> 5] = s;
    __syncthreads();
    if (threadIdx.x < 32) {
        float t = red[threadIdx.x];
#pragma unroll
        for (int off = 16; off > 0; off >>= 1)
            t += __shfl_xor_sync(0xffffffffu, t, off);
        if (threadIdx.x == 0) g_mu = t / (float)(On * CKK);
    }
}

// ---------------------------------------------------------------------------
// Main kernel. grid = (OG=8, NBAND=14, Bn=4) = 448 blocks, 224 threads.
// Thread = one output pixel in a 4x56 band, TO=8 output channels.
// Inner math in packed fp16; per-channel chunk sums flushed to fp32.
// ---------------------------------------------------------------------------
__global__ __launch_bounds__(THREADS, 4)
void approx_conv_kernel(const float* __restrict__ x,
                        const float* __restrict__ w,
                        float* __restrict__ out) {
    __shared__ __align__(16) __half ws[CKK * TO];   // 4608 B, [ck][8ch]
    __shared__ __align__(16) __half2 xs[XS_SIZE];   // 22272 B, dup'd pairs

    const int tid   = threadIdx.x;
    const int og    = blockIdx.x;
    const int band  = blockIdx.y;
    const int b     = blockIdx.z;
    const int obase = og * TO;
    const int hbase = band * TH;

    // Weights: ws[ck*8 + oo] = half(w[(obase+oo)*CKK + ck])
    for (int i = tid; i < CKK * TO; i += THREADS) {
        int ck = i / TO;
        int oo = i % TO;
        ws[i] = __float2half(w[(obase + oo) * CKK + ck]);
    }

    const int row = tid / Wn;  // 0..3
    const int col = tid % Wn;  // 0..55

    float f0 = 0.f, f1 = 0.f, f2 = 0.f, f3 = 0.f;
    float f4 = 0.f, f5 = 0.f, f6 = 0.f, f7 = 0.f;

    for (int ch = 0; ch < NCHUNK; ch++) {
        __syncthreads();
        // Stage 16 channels of x as duplicated half2, padded 6x58
        for (int i = tid; i < XS_SIZE; i += THREADS) {
            int cc  = i / XS_PLANE;
            int rem = i % XS_PLANE;
            int r   = rem / XS_COLS;
            int cl  = rem % XS_COLS;
            int gh  = hbase + r - 1;
            int gw  = cl - 1;
            float v = 0.f;
            if (gh >= 0 && gh < Hn && gw >= 0 && gw < Wn)
                v = x[((b * Cn + ch * CCHUNK + cc) * Hn + gh) * Wn + gw];
            xs[i] = __float2half2_rn(v);
        }
        __syncthreads();

#pragma unroll 2
        for (int cc = 0; cc < CCHUNK; cc++) {
            const __half2* xbase = &xs[cc * XS_PLANE + row * XS_COLS + col];
            __half2 xv[9];
#pragma unroll
            for (int kh = 0; kh < 3; kh++)
#pragma unroll
                for (int kw = 0; kw < 3; kw++)
                    xv[kh * 3 + kw] = xbase[kh * XS_COLS + kw];

            const uint4* wp = reinterpret_cast<const uint4*>(
                &ws[(ch * CCHUNK + cc) * KK * TO]);

            __half2 h0, h1, h2, h3;
            {
                uint4 wv = wp[0];   // LDS.128 broadcast: 8 weights
                h0 = __hmin2(xv[0], *reinterpret_cast<__half2*>(&wv.x));
                h1 = __hmin2(xv[0], *reinterpret_cast<__half2*>(&wv.y));
                h2 = __hmin2(xv[0], *reinterpret_cast<__half2*>(&wv.z));
                h3 = __hmin2(xv[0], *reinterpret_cast<__half2*>(&wv.w));
            }
#pragma unroll
            for (int p = 1; p < 9; p++) {
                uint4 wv = wp[p];
                h0 = __hadd2(h0, __hmin2(xv[p], *reinterpret_cast<__half2*>(&wv.x)));
                h1 = __hadd2(h1, __hmin2(xv[p], *reinterpret_cast<__half2*>(&wv.y)));
                h2 = __hadd2(h2, __hmin2(xv[p], *reinterpret_cast<__half2*>(&wv.z)));
                h3 = __hadd2(h3, __hmin2(xv[p], *reinterpret_cast<__half2*>(&wv.w)));
            }
            // flush 9-term fp16 chunk into fp32 accumulators
            f0 += __low2float(h0);  f1 += __high2float(h0);
            f2 += __low2float(h1);  f3 += __high2float(h1);
            f4 += __low2float(h2);  f5 += __high2float(h2);
            f6 += __low2float(h3);  f7 += __high2float(h3);
        }
    }

    const float mu = g_mu;
    const int h = hbase + row;
    float* dst = &out[((b * On + obase) * Hn + h) * Wn + col];
    dst[0 * Hn * Wn] = mu * f0;
    dst[1 * Hn * Wn] = mu * f1;
    dst[2 * Hn * Wn] = mu * f2;
    dst[3 * Hn * Wn] = mu * f3;
    dst[4 * Hn * Wn] = mu * f4;
    dst[5 * Hn * Wn] = mu * f5;
    dst[6 * Hn * Wn] = mu * f6;
    dst[7 * Hn * Wn] = mu * f7;
}

extern "C" void kernel_launch(void* const* d_in, const int* in_sizes, int n_in,
                              void* d_out, int out_size) {
    const float* x = (const float*)d_in[0];
    const float* w = (const float*)d_in[1];
    float* out = (float*)d_out;

    mu_kernel<<<1, 1024>>>(w);

    dim3 grid(OG, NBAND, Bn);
    approx_conv_kernel<<<grid, THREADS>>>(x, w, out);
}